// round 16
// baseline (speedup 1.0000x reference)
#include <cuda_runtime.h>
#include <math.h>

#define NB   2048
#define NDIM 128
#define MLZ  10
#define KAPPA 0.276f
#define TRI  8256      // 128*129/2
#define LPAD 8448      // packed tri, rows padded to multiple of 4 floats

// smem: Lp[8448] | vcur[128] | vprev[128] | yv[128] | slab[512] (slab0 aliases U1s)
#define SMEM_FLOATS (LPAD + 3 * NDIM + 4 * NDIM)
#define SMEM_BYTES  (SMEM_FLOATS * 4)

__device__ float    g_scr[2 * NB];   // [0..NB) max^2, [NB..2NB) min^2
__device__ unsigned g_ctr = 0;

// Compile-time map: packed-tri index k -> padded-layout float offset.
struct alignas(16) OffTab {
    unsigned short v[TRI];
    constexpr OffTab() : v() {
        int i = 0, j = 0;
        for (int k = 0; k < TRI; k++) {
            int gi = i >> 2, ri = i & 3;
            v[k] = (unsigned short)(4 * (gi + 1) * (2 * gi + ri) + j);
            if (++j > i) { ++i; j = 0; }
        }
    }
};
__device__ static const OffTab g_off = OffTab();

union F2 { float2 f; unsigned long long u; };

// Single-sync block reduce. SAFETY: consecutive uses of the SAME buf are
// separated by >=1 other __syncthreads() at every call site (redA/redB ping-pong).
__device__ __forceinline__ float blockReduceSum1(float v, float* buf, int tid) {
    #pragma unroll
    for (int o = 16; o > 0; o >>= 1)
        v += __shfl_xor_sync(0xffffffffu, v, o);
    if ((tid & 31) == 0) buf[tid >> 5] = v;
    __syncthreads();
    return (buf[0] + buf[1]) + (buf[2] + buf[3]);
}

// #eigenvalues of the 10x10 symmetric tridiagonal < x (Sturm / LDL recurrence).
__device__ __forceinline__ int sturm_count(const float* a, const float* b2, float x) {
    float q = a[0] - x;
    int c = (q < 0.0f);
    #pragma unroll
    for (int i = 1; i < MLZ; i++) {
        float d = q;
        if (fabsf(d) < 1e-25f) d = (d < 0.0f) ? -1e-25f : 1e-25f;
        q = (a[i] - x) - __fdividef(b2[i - 1], d);
        c += (q < 0.0f);
    }
    return c;
}

__global__ __launch_bounds__(128, 6)
void spectrum_kernel(const float* __restrict__ net_out,
                     const float* __restrict__ U1,
                     const float* __restrict__ vin,
                     float* __restrict__ out) {
    extern __shared__ float sm[];
    float* Lp    = sm;                 // row i (g=i>>2, rm=i&3) at float4 idx (g+1)*(2g+rm)
    float* vcur  = sm + LPAD;
    float* vprev = vcur + NDIM;
    float* yv    = vprev + NDIM;       // y during col phase; t after combine
    float* slab  = yv + NDIM;          // 4 x 128 col-phase partials
    float* U1s   = slab;               // alias slab0 (setup only)

    __shared__ float redA[4], redB[4];
    __shared__ float alph[MLZ], bet[MLZ], sc[4];
    __shared__ int   amLast;

    const int tid  = threadIdx.x;
    const int b    = blockIdx.x;
    const int wid  = tid >> 5;
    const int lane = tid & 31;

    // ---- zero ONLY the row pads (3-rm floats at the end of row tid) ----
    {
        const int i = tid, g2 = i >> 2, rm = i & 3;
        float* rowL = Lp + 4 * (g2 + 1) * (2 * g2 + rm);
        #pragma unroll
        for (int p = 0; p < 3; p++)
            if (rm + 1 + p <= 3) rowL[i + 1 + p] = 0.0f;
    }
    U1s[tid] = U1[(size_t)b * NDIM + tid];
    float v0 = vin[(size_t)b * NDIM + tid];

    // ---- build padded packed Lp via precomputed offset table ----
    {
        const float4*  src4 = (const float4*)(net_out + (size_t)b * TRI);
        const ushort4* off4 = (const ushort4*)g_off.v;
        #pragma unroll 4
        for (int idx = tid; idx < TRI / 4; idx += 128) {
            float4  v4 = src4[idx];
            ushort4 o  = off4[idx];
            Lp[o.x] = v4.x;
            Lp[o.y] = v4.y;
            Lp[o.z] = v4.z;
            Lp[o.w] = v4.w;
        }
    }

    // vn = v / ||v||  (this reduce's barrier publishes Lp/U1s too)
    float nrm = sqrtf(blockReduceSum1(v0 * v0, redA, tid));
    vcur[tid]  = v0 / nrm;
    vprev[tid] = 0.0f;

    // ---- dd_opt stencil constants (U1s read ONLY here; slab reuse after) ----
    const int ii = tid >> 4, jj = (tid >> 1) & 7, cc = tid & 1;
    const int xip = (((ii + 1) & 7) << 4) | (jj << 1) | cc;
    const int xim = (((ii - 1) & 7) << 4) | (jj << 1) | cc;
    const int xjp = (ii << 4) | (((jj + 1) & 7) << 1) | cc;
    const int xjm = (ii << 4) | (((jj - 1) & 7) << 1) | cc;
    const float c_u0  = U1s[((ii << 3) + jj) << 1];
    const float c_u1  = U1s[(((ii << 3) + jj) << 1) + 1];
    const float c_u0m = U1s[((((ii - 1) & 7) << 3) + jj) << 1];
    const float c_u1m = U1s[(((ii << 3) + ((jj - 1) & 7)) << 1) + 1];

    // loop-invariant matvec bases
    const int g   = tid >> 2;
    const int rb4 = (g + 1) * (2 * g + (tid & 3));    // row matvec: row tid base (f4)
    const int m0  = wid << 3;                          // col phase: first row-group
    const int a0  = ((m0 * (m0 + 1)) << 1) + lane;     // base of group m0 (f4 units)
    const float4* Lr4 = (const float4*)Lp;
    const float4* yv4 = (const float4*)yv;

    float beta = 0.0f;
    __syncthreads();   // vcur/vprev + U1s-consts settled before mainloop

    for (int step = 0; step < MLZ; step++) {
        // ---- y = D x (hop stencil) ----
        {
            float xc  = vcur[tid];
            float hop = c_u0  * vcur[xip] + c_u1  * vcur[xjp]
                      + c_u0m * vcur[xim] + c_u1m * vcur[xjm];
            yv[tid] = xc - KAPPA * hop;
        }
        __syncthreads();                                    // S1

        // ---- col phase, row-scan: warp w scans rows 32w..32w+31, lane owns
        //      columns 4l..4l+3 via one LDS.128 per row.
        //      4 INDEPENDENT second-order address counters:
        //        c_k(grp) = base(grp) + k*s(grp);  Δc_k = 4s + k;  s4 += 4. ----
        {
            float4 aA = make_float4(0.f, 0.f, 0.f, 0.f);
            float4 aB = make_float4(0.f, 0.f, 0.f, 0.f);
            int s  = m0 + 1;                  // m+1 for current group
            int s4 = (m0 + 1) << 2;           // 4*s
            int c0 = a0;
            int c1 = a0 + s;
            int c2 = a0 + 2 * s;
            int c3 = a0 + 3 * s;
            #pragma unroll
            for (int grp = 0; grp < 8; grp++) {
                float4 y4 = yv4[m0 + grp];     // uniform broadcast
                bool act = (lane < s);         // lane <= m; diag pads are zero
                if (act) {
                    float4 l0 = Lr4[c0];
                    float4 l1 = Lr4[c1];
                    float4 l2 = Lr4[c2];
                    float4 l3 = Lr4[c3];
                    aA.x += l0.x * y4.x; aA.y += l0.y * y4.x;
                    aA.z += l0.z * y4.x; aA.w += l0.w * y4.x;
                    aB.x += l1.x * y4.y; aB.y += l1.y * y4.y;
                    aB.z += l1.z * y4.y; aB.w += l1.w * y4.y;
                    aA.x += l2.x * y4.z; aA.y += l2.y * y4.z;
                    aA.z += l2.z * y4.z; aA.w += l2.w * y4.z;
                    aB.x += l3.x * y4.w; aB.y += l3.y * y4.w;
                    aB.z += l3.z * y4.w; aB.w += l3.w * y4.w;
                }
                c0 += s4; c1 += s4 + 1; c2 += s4 + 2; c3 += s4 + 3;
                s4 += 4;
                s  += 1;
            }
            float4 t;
            t.x = aA.x + aB.x; t.y = aA.y + aB.y;
            t.z = aA.z + aB.z; t.w = aA.w + aB.w;
            *(float4*)(slab + (wid << 7) + (lane << 2)) = t;
        }
        __syncthreads();                                    // S2

        // ---- combine: t[j] = sum of 4 warp partials; store into yv (y dead) ----
        yv[tid] = (slab[tid] + slab[NDIM + tid])
                + (slab[2 * NDIM + tid] + slab[3 * NDIM + tid]);
        __syncthreads();                                    // S2b

        // ---- w_i = sum_{j<=i} L[i,j] t_j : f4 loads + packed f32x2 FMA ----
        float wacc;
        {
            F2 accA, accB; accA.u = 0ull; accB.u = 0ull;
            #pragma unroll 4
            for (int q = 0; q <= g; q++) {
                float4 l  = Lr4[rb4 + q];
                float4 t4 = yv4[q];
                F2 la, lb, ta, tb;
                la.f = make_float2(l.x,  l.y);  lb.f = make_float2(l.z,  l.w);
                ta.f = make_float2(t4.x, t4.y); tb.f = make_float2(t4.z, t4.w);
                asm("fma.rn.f32x2 %0, %1, %2, %0;" : "+l"(accA.u) : "l"(la.u), "l"(ta.u));
                asm("fma.rn.f32x2 %0, %1, %2, %0;" : "+l"(accB.u) : "l"(lb.u), "l"(tb.u));
            }
            wacc = (accA.f.x + accB.f.x) + (accA.f.y + accB.f.y);
        }

        // ---- Lanczos recurrence (explicit, matches reference math) ----
        float al = blockReduceSum1(wacc * vcur[tid], redA, tid);     // S3
        float wn = wacc - al * vcur[tid] - beta * vprev[tid];
        float bn = sqrtf(blockReduceSum1(wn * wn, redB, tid));       // S4
        if (tid == 0) { alph[step] = al; bet[step] = bn; }
        vprev[tid] = vcur[tid];
        vcur[tid]  = wn / (bn + 1e-30f);
        beta = bn;
        __syncthreads();                                    // S5
    }

    // ---- eigen tail: warp per target, 32-way multisection (8 iters ~ 40 bits) ----
    {
        float a[MLZ], b2[MLZ - 1];
        #pragma unroll
        for (int i = 0; i < MLZ; i++) a[i] = alph[i];
        #pragma unroll
        for (int i = 0; i < MLZ - 1; i++) { float bb = bet[i]; b2[i] = bb * bb; }

        float lo = 3.0e38f, hi = -3.0e38f;
        #pragma unroll
        for (int i = 0; i < MLZ; i++) {
            float rad = 0.0f;
            if (i > 0)       rad += fabsf(bet[i - 1]);
            if (i < MLZ - 1) rad += fabsf(bet[i]);
            lo = fminf(lo, a[i] - rad);
            hi = fmaxf(hi, a[i] + rad);
        }

        int nneg = sturm_count(a, b2, 0.0f);
        int k;
        if      (wid == 0) k = 0;
        else if (wid == 1) k = MLZ - 1;
        else if (wid == 2) { k = nneg - 1; if (k < 0) k = 0; if (k > MLZ - 1) k = MLZ - 1; }
        else               { k = nneg;     if (k > MLZ - 1) k = MLZ - 1; }

        #pragma unroll 1
        for (int it = 0; it < 8; it++) {
            float wdt = (hi - lo) * (1.0f / 33.0f);
            float x   = lo + wdt * (float)(lane + 1);
            int   c   = sturm_count(a, b2, x);
            unsigned m = __ballot_sync(0xffffffffu, c > k);
            int idx = (m == 0u) ? 32 : (__ffs(m) - 1);
            float nlo = lo + wdt * (float)idx;
            float nhi = (idx == 32) ? hi : lo + wdt * (float)(idx + 1);
            lo = nlo; hi = nhi;
        }
        if (lane == 0) sc[wid] = fabsf(0.5f * (lo + hi));
    }
    __syncthreads();

    if (tid == 0) {
        float mx = fmaxf(sc[0], sc[1]);   // max |lambda|
        float mn = fminf(sc[2], sc[3]);   // min |lambda|
        g_scr[b]      = mx * mx;
        g_scr[NB + b] = mn * mn;
        __threadfence();
        unsigned t = atomicAdd(&g_ctr, 1u);
        amLast = (t == NB - 1);
    }
    __syncthreads();

    // ---- last CTA reduces all batches (fixed order => deterministic) ----
    if (amLast) {
        __threadfence();
        const volatile float* scr = g_scr;
        float s1 = 0.0f, s2 = 0.0f;
        for (int i = tid; i < NB; i += 128) { s1 += scr[i]; s2 += scr[NB + i]; }
        float S1 = blockReduceSum1(s1, redA, tid);
        float S2 = blockReduceSum1(s2, redB, tid);
        if (tid == 0) {
            out[0] = (S1 - S2) * (1.0f / (float)NB);
            g_ctr = 0;   // reset for next graph replay
        }
    }
}

extern "C" void kernel_launch(void* const* d_in, const int* in_sizes, int n_in,
                              void* d_out, int out_size) {
    const float* net_out = (const float*)d_in[0];
    const float* U1      = (const float*)d_in[1];
    const float* v       = (const float*)d_in[2];
    (void)in_sizes; (void)n_in; (void)out_size;

    spectrum_kernel<<<NB, 128, SMEM_BYTES>>>(net_out, U1, v, (float*)d_out);
}

// round 17
// speedup vs baseline: 1.0614x; 1.0614x over previous
#include <cuda_runtime.h>
#include <math.h>

#define NB   2048
#define NDIM 128
#define MLZ  10
#define KAPPA 0.276f
#define TRI  8256      // 128*129/2
#define LPAD 8448      // packed tri, rows padded to multiple of 4 floats

// smem: Lp[8448] | vcur[128] | vprev[128] | yv[128] | tv[128] | U1s[128]
#define SMEM_FLOATS (LPAD + 5 * NDIM)
#define SMEM_BYTES  (SMEM_FLOATS * 4)

__device__ float    g_scr[2 * NB];   // [0..NB) max^2, [NB..2NB) min^2
__device__ unsigned g_ctr = 0;

// Compile-time map: packed-tri index k -> padded-layout float offset.
struct alignas(16) OffTab {
    unsigned short v[TRI];
    constexpr OffTab() : v() {
        int i = 0, j = 0;
        for (int k = 0; k < TRI; k++) {
            int gi = i >> 2, ri = i & 3;
            v[k] = (unsigned short)(4 * (gi + 1) * (2 * gi + ri) + j);
            if (++j > i) { ++i; j = 0; }
        }
    }
};
__device__ static const OffTab g_off = OffTab();

union F2 { float2 f; unsigned long long u; };

// Single-sync block reduce. SAFETY: consecutive uses of the SAME buf are
// separated by >=1 other __syncthreads() at every call site (redA/redB ping-pong).
__device__ __forceinline__ float blockReduceSum1(float v, float* buf, int tid) {
    #pragma unroll
    for (int o = 16; o > 0; o >>= 1)
        v += __shfl_xor_sync(0xffffffffu, v, o);
    if ((tid & 31) == 0) buf[tid >> 5] = v;
    __syncthreads();
    return (buf[0] + buf[1]) + (buf[2] + buf[3]);
}

// #eigenvalues of the 10x10 symmetric tridiagonal < x (Sturm / LDL recurrence).
__device__ __forceinline__ int sturm_count(const float* a, const float* b2, float x) {
    float q = a[0] - x;
    int c = (q < 0.0f);
    #pragma unroll
    for (int i = 1; i < MLZ; i++) {
        float d = q;
        if (fabsf(d) < 1e-25f) d = (d < 0.0f) ? -1e-25f : 1e-25f;
        q = (a[i] - x) - __fdividef(b2[i - 1], d);
        c += (q < 0.0f);
    }
    return c;
}

__global__ __launch_bounds__(128, 6)
void spectrum_kernel(const float* __restrict__ net_out,
                     const float* __restrict__ U1,
                     const float* __restrict__ vin,
                     float* __restrict__ out) {
    extern __shared__ float sm[];
    float* Lp    = sm;                 // row i (g=i>>2, rm=i&3) at float4 idx (g+1)*(2g+rm)
    float* vcur  = sm + LPAD;
    float* vprev = vcur + NDIM;
    float* yv    = vprev + NDIM;
    float* tv    = yv + NDIM;
    float* U1s   = tv + NDIM;

    __shared__ float redA[4], redB[4];
    __shared__ float alph[MLZ], bet[MLZ], sc[4];
    __shared__ int   amLast;

    const int tid = threadIdx.x;
    const int b   = blockIdx.x;

    // ---- zero ONLY the row pads (3-rm floats at the end of row tid) ----
    // After this, every in-row position j>i of row i is EXACTLY 0.0f.
    {
        const int i = tid, g2 = i >> 2, rm = i & 3;
        float* rowL = Lp + 4 * (g2 + 1) * (2 * g2 + rm);
        #pragma unroll
        for (int p = 0; p < 3; p++)
            if (rm + 1 + p <= 3) rowL[i + 1 + p] = 0.0f;
    }
    U1s[tid] = U1[(size_t)b * NDIM + tid];
    float v0 = vin[(size_t)b * NDIM + tid];

    // ---- build padded packed Lp via precomputed offset table ----
    {
        const float4*  src4 = (const float4*)(net_out + (size_t)b * TRI);
        const ushort4* off4 = (const ushort4*)g_off.v;
        #pragma unroll 4
        for (int idx = tid; idx < TRI / 4; idx += 128) {
            float4  v4 = src4[idx];
            ushort4 o  = off4[idx];
            Lp[o.x] = v4.x;
            Lp[o.y] = v4.y;
            Lp[o.z] = v4.z;
            Lp[o.w] = v4.w;
        }
    }

    // vn = v / ||v||  (this reduce's barrier publishes Lp/U1s too)
    float nrm = sqrtf(blockReduceSum1(v0 * v0, redA, tid));
    vcur[tid]  = v0 / nrm;
    vprev[tid] = 0.0f;

    // ---- dd_opt stencil constants ----
    const int ii = tid >> 4, jj = (tid >> 1) & 7, cc = tid & 1;
    const int xip = (((ii + 1) & 7) << 4) | (jj << 1) | cc;
    const int xim = (((ii - 1) & 7) << 4) | (jj << 1) | cc;
    const int xjp = (ii << 4) | (((jj + 1) & 7) << 1) | cc;
    const int xjm = (ii << 4) | (((jj - 1) & 7) << 1) | cc;
    const float c_u0  = U1s[((ii << 3) + jj) << 1];
    const float c_u1  = U1s[(((ii << 3) + jj) << 1) + 1];
    const float c_u0m = U1s[((((ii - 1) & 7) << 3) + jj) << 1];
    const float c_u1m = U1s[(((ii << 3) + ((jj - 1) & 7)) << 1) + 1];

    // loop-invariant matvec bases
    const int g    = tid >> 2;
    const int rb4  = (g + 1) * (2 * g + (tid & 3));   // row matvec: this thread's row base (f4)
    const int mb0  = (tid & ~31) >> 2;                // col matvec: warp-uniform first i-group
    const float4* Lr4 = (const float4*)Lp;
    const float4* yv4 = (const float4*)yv;
    const float4* tv4 = (const float4*)tv;

    float beta = 0.0f;
    __syncthreads();   // vcur/vprev visible before hop reads neighbors

    for (int step = 0; step < MLZ; step++) {
        // ---- y = D x (hop stencil) ----
        {
            float xc  = vcur[tid];
            float hop = c_u0  * vcur[xip] + c_u1  * vcur[xjp]
                      + c_u0m * vcur[xim] + c_u1m * vcur[xjm];
            yv[tid] = xc - KAPPA * hop;
        }
        __syncthreads();                                    // S1

        // ---- t_j = sum_{i>=j} L[i,j] y_i ----
        // warp-synchronized rows i = 4m+k; lane j = tid -> consecutive floats (conflict-free).
        // 4 independent second-order address counters, no serial chain through the loads.
        // Bounds insight: rows of group m are in-bounds for lane j iff g <= m (ONE
        // predicate per group, not four); in-bounds entries with i < j read the
        // exact 0.0f pads and contribute bitwise-exact zero.
        {
            float a0 = 0.f, a1 = 0.f, a2 = 0.f, a3 = 0.f;
            int b0 = (((mb0 + 1) * (2 * mb0    )) << 2) + tid;
            int b1 = (((mb0 + 1) * (2 * mb0 + 1)) << 2) + tid;
            int b2 = (((mb0 + 1) * (2 * mb0 + 2)) << 2) + tid;
            int b3 = (((mb0 + 1) * (2 * mb0 + 3)) << 2) + tid;
            int dinc = (mb0 << 4) + 16;

            // head: 8 diagonal-crossing groups; single per-group bound predicate
            #pragma unroll 1
            for (int m = mb0; m < mb0 + 8; m++) {
                float4 y4 = yv4[m];
                if (g <= m) {
                    float l0 = Lp[b0], l1 = Lp[b1], l2 = Lp[b2], l3 = Lp[b3];
                    a0 += l0 * y4.x;
                    a1 += l1 * y4.y;
                    a2 += l2 * y4.z;
                    a3 += l3 * y4.w;
                }
                b0 += dinc; b1 += dinc + 4; b2 += dinc + 8; b3 += dinc + 12;
                dinc += 16;
            }
            // tail: all rows in-bounds for every lane (no predicates)
            #pragma unroll 4
            for (int m = mb0 + 8; m < 32; m++) {
                float4 y4 = yv4[m];
                a0 += Lp[b0] * y4.x;
                a1 += Lp[b1] * y4.y;
                a2 += Lp[b2] * y4.z;
                a3 += Lp[b3] * y4.w;
                b0 += dinc; b1 += dinc + 4; b2 += dinc + 8; b3 += dinc + 12;
                dinc += 16;
            }
            tv[tid] = (a0 + a1) + (a2 + a3);
        }
        __syncthreads();                                    // S2

        // ---- w_i = sum_{j<=i} L[i,j] t_j : float4 loads + packed f32x2 FMA ----
        float wacc;
        {
            F2 accA, accB; accA.u = 0ull; accB.u = 0ull;
            #pragma unroll 4
            for (int q = 0; q <= g; q++) {
                float4 l  = Lr4[rb4 + q];
                float4 t4 = tv4[q];
                F2 la, lb, ta, tb;
                la.f = make_float2(l.x,  l.y);  lb.f = make_float2(l.z,  l.w);
                ta.f = make_float2(t4.x, t4.y); tb.f = make_float2(t4.z, t4.w);
                asm("fma.rn.f32x2 %0, %1, %2, %0;" : "+l"(accA.u) : "l"(la.u), "l"(ta.u));
                asm("fma.rn.f32x2 %0, %1, %2, %0;" : "+l"(accB.u) : "l"(lb.u), "l"(tb.u));
            }
            wacc = (accA.f.x + accB.f.x) + (accA.f.y + accB.f.y);
        }

        // ---- Lanczos recurrence (explicit, matches reference math) ----
        float al = blockReduceSum1(wacc * vcur[tid], redA, tid);     // S3
        float wn = wacc - al * vcur[tid] - beta * vprev[tid];
        float bn = sqrtf(blockReduceSum1(wn * wn, redB, tid));       // S4
        if (tid == 0) { alph[step] = al; bet[step] = bn; }
        vprev[tid] = vcur[tid];
        vcur[tid]  = wn / (bn + 1e-30f);
        beta = bn;
        __syncthreads();                                    // S5
    }

    // ---- eigen tail: warp per target, 32-way multisection (8 iters ~ 40 bits) ----
    {
        const int wid  = tid >> 5;
        const int lane = tid & 31;

        float a[MLZ], b2[MLZ - 1];
        #pragma unroll
        for (int i = 0; i < MLZ; i++) a[i] = alph[i];
        #pragma unroll
        for (int i = 0; i < MLZ - 1; i++) { float bb = bet[i]; b2[i] = bb * bb; }

        float lo = 3.0e38f, hi = -3.0e38f;
        #pragma unroll
        for (int i = 0; i < MLZ; i++) {
            float rad = 0.0f;
            if (i > 0)       rad += fabsf(bet[i - 1]);
            if (i < MLZ - 1) rad += fabsf(bet[i]);
            lo = fminf(lo, a[i] - rad);
            hi = fmaxf(hi, a[i] + rad);
        }

        int nneg = sturm_count(a, b2, 0.0f);
        int k;
        if      (wid == 0) k = 0;
        else if (wid == 1) k = MLZ - 1;
        else if (wid == 2) { k = nneg - 1; if (k < 0) k = 0; if (k > MLZ - 1) k = MLZ - 1; }
        else               { k = nneg;     if (k > MLZ - 1) k = MLZ - 1; }

        #pragma unroll 1
        for (int it = 0; it < 8; it++) {
            float wdt = (hi - lo) * (1.0f / 33.0f);
            float x   = lo + wdt * (float)(lane + 1);
            int   c   = sturm_count(a, b2, x);
            unsigned m = __ballot_sync(0xffffffffu, c > k);
            int idx = (m == 0u) ? 32 : (__ffs(m) - 1);
            float nlo = lo + wdt * (float)idx;
            float nhi = (idx == 32) ? hi : lo + wdt * (float)(idx + 1);
            lo = nlo; hi = nhi;
        }
        if (lane == 0) sc[wid] = fabsf(0.5f * (lo + hi));
    }
    __syncthreads();

    if (tid == 0) {
        float mx = fmaxf(sc[0], sc[1]);   // max |lambda|
        float mn = fminf(sc[2], sc[3]);   // min |lambda|
        g_scr[b]      = mx * mx;
        g_scr[NB + b] = mn * mn;
        __threadfence();
        unsigned t = atomicAdd(&g_ctr, 1u);
        amLast = (t == NB - 1);
    }
    __syncthreads();

    // ---- last CTA reduces all batches (fixed order => deterministic) ----
    if (amLast) {
        __threadfence();
        const volatile float* scr = g_scr;
        float s1 = 0.0f, s2 = 0.0f;
        for (int i = tid; i < NB; i += 128) { s1 += scr[i]; s2 += scr[NB + i]; }
        float S1 = blockReduceSum1(s1, redA, tid);
        float S2 = blockReduceSum1(s2, redB, tid);
        if (tid == 0) {
            out[0] = (S1 - S2) * (1.0f / (float)NB);
            g_ctr = 0;   // reset for next graph replay
        }
    }
}

extern "C" void kernel_launch(void* const* d_in, const int* in_sizes, int n_in,
                              void* d_out, int out_size) {
    const float* net_out = (const float*)d_in[0];
    const float* U1      = (const float*)d_in[1];
    const float* v       = (const float*)d_in[2];
    (void)in_sizes; (void)n_in; (void)out_size;

    spectrum_kernel<<<NB, 128, SMEM_BYTES>>>(net_out, U1, v, (float*)d_out);
}